// round 5
// baseline (speedup 1.0000x reference)
#include <cuda_runtime.h>
#include <cuda_bf16.h>
#include <math.h>
#include <stdint.h>

#define C_CH   128
#define N_PTS  32768
#define K_PWL  20
#define LATENT 8
#define HID    8

// ---------------- scratch (static device memory; no allocations) ----------------
__device__ float g_x[(size_t)C_CH * N_PTS];     // raw x MLP outputs [C][N]
__device__ float g_e[(size_t)C_CH * N_PTS];     // raw e MLP outputs [C][N]
__device__ float g_yp[C_CH * K_PWL];            // per-channel sorted/flipped breakpoint ys
__device__ unsigned int g_minbits[C_CH];
__device__ unsigned int g_maxbits[C_CH];
__device__ float g_psum[2048];
__device__ float g_psumsq[2048];

// xp = linspace(0,1,20) in f32
#define XPV(k) ((float)((double)(k) / 19.0))
__constant__ float c_xp[K_PWL] = {
    XPV(0), XPV(1), XPV(2), XPV(3), XPV(4), XPV(5), XPV(6), XPV(7), XPV(8), XPV(9),
    XPV(10), XPV(11), XPV(12), XPV(13), XPV(14), XPV(15), XPV(16), XPV(17), XPV(18), XPV(19)
};

// ---------------- helpers ----------------
__device__ __forceinline__ unsigned int fenc(float f) {
    unsigned int u = __float_as_uint(f);
    return (u >> 31) ? ~u : (u | 0x80000000u);
}
__device__ __forceinline__ float fdec(unsigned int u) {
    return (u & 0x80000000u) ? __uint_as_float(u & 0x7FFFFFFFu) : __uint_as_float(~u);
}

// Fast, tight-absolute-error tanh: (e^{2x}-1)/(e^{2x}+1). abs err ~1e-7.
__device__ __forceinline__ float tanh_fast(float x) {
    x = fminf(fmaxf(x, -30.0f), 30.0f);
    float t = __expf(2.0f * x);
    return __fdividef(t - 1.0f, t + 1.0f);
}

// ---------------- K1: PWL generator (tiny) + min/max init ----------------
__global__ void gen_pwl_kernel(const float* __restrict__ zf,
                               const float* __restrict__ Wf1, const float* __restrict__ bf1,
                               const float* __restrict__ Wf2, const float* __restrict__ bf2,
                               const void* __restrict__ dirs_raw) {
    int c = threadIdx.x;  // 128 threads, one per channel
    __shared__ int mode;  // 0 = int32, 1 = uint8/bool, 2 = float32
    if (c == 0) {
        const unsigned char* b = (const unsigned char*)dirs_raw;
        bool off_zero = true, all01 = true;
        for (int i = 0; i < 128; i++) {
            unsigned char v = b[i];
            if ((i & 3) != 0 && v != 0) off_zero = false;
            if (v > 1) all01 = false;
        }
        mode = off_zero ? 0 : (all01 ? 1 : 2);
    }
    __syncthreads();

    float z[LATENT];
#pragma unroll
    for (int i = 0; i < LATENT; i++) z[i] = zf[c * LATENT + i];

    float h[HID];
#pragma unroll
    for (int j = 0; j < HID; j++) h[j] = bf1[j];
#pragma unroll
    for (int i = 0; i < LATENT; i++)
#pragma unroll
        for (int j = 0; j < HID; j++) h[j] = fmaf(z[i], Wf1[i * HID + j], h[j]);
#pragma unroll
    for (int j = 0; j < HID; j++) h[j] = tanhf(h[j]);

    float pts[K_PWL];
#pragma unroll
    for (int k = 0; k < K_PWL; k++) {
        float s = bf2[k];
#pragma unroll
        for (int j = 0; j < HID; j++) s = fmaf(h[j], Wf2[j * K_PWL + k], s);
        pts[k] = tanhf(s);
    }
    // insertion sort ascending
    for (int a = 1; a < K_PWL; a++) {
        float v = pts[a];
        int b = a - 1;
        while (b >= 0 && pts[b] > v) { pts[b + 1] = pts[b]; b--; }
        pts[b + 1] = v;
    }
    bool dir;
    if (mode == 0)      dir = ((const int*)dirs_raw)[c] != 0;
    else if (mode == 1) dir = ((const unsigned char*)dirs_raw)[c] != 0;
    else                dir = ((const float*)dirs_raw)[c] > 0.5f;

    for (int k = 0; k < K_PWL; k++)
        g_yp[c * K_PWL + k] = dir ? pts[k] : pts[K_PWL - 1 - k];

    g_minbits[c] = 0xFFFFFFFFu;
    g_maxbits[c] = 0u;
}

// ---------------- K2: fused x/e MLP pass (blockIdx.z selects) ----------------
// z==0: x MLP + per-channel min/max atomics
// z==1: e MLP + per-block sum/sumsq partials
__global__ void __launch_bounds__(256) pass_xe_kernel(
    const float* __restrict__ zx,
    const float* __restrict__ Wx1, const float* __restrict__ bx1,
    const float* __restrict__ Wx2, const float* __restrict__ bx2,
    const float* __restrict__ ze,
    const float* __restrict__ We1, const float* __restrict__ be1,
    const float* __restrict__ We2, const float* __restrict__ be2) {
    const bool is_e = (blockIdx.z != 0);
    const float* __restrict__ src = is_e ? ze : zx;
    const float* __restrict__ W1p = is_e ? We1 : Wx1;
    const float* __restrict__ b1p = is_e ? be1 : bx1;
    const float* __restrict__ W2p = is_e ? We2 : Wx2;
    const float* __restrict__ b2p = is_e ? be2 : bx2;
    float* __restrict__ dst = is_e ? g_e : g_x;

    float W1r[64];
#pragma unroll
    for (int i = 0; i < 64; i++) W1r[i] = __ldg(W1p + i);
    float b1r[HID], W2r[HID];
#pragma unroll
    for (int j = 0; j < HID; j++) { b1r[j] = __ldg(b1p + j); W2r[j] = __ldg(W2p + j); }
    float b2r = __ldg(b2p);

    const int c = blockIdx.y;
    const int tid = threadIdx.x;
    const size_t base = (size_t)c * N_PTS;
    const int n0 = blockIdx.x * 2048;

    float lmin = 1e30f, lmax = -1e30f;   // x stats
    float ls = 0.0f, lq = 0.0f;          // e stats
#pragma unroll
    for (int k = 0; k < 8; k++) {
        int n = n0 + k * 256 + tid;
        const float4* p = reinterpret_cast<const float4*>(src + (base + n) * LATENT);
        float4 a = __ldcs(p);          // streaming: don't pollute L2
        float4 bq = __ldcs(p + 1);
        float z[8] = {a.x, a.y, a.z, a.w, bq.x, bq.y, bq.z, bq.w};
        float h[HID];
#pragma unroll
        for (int j = 0; j < HID; j++) h[j] = b1r[j];
#pragma unroll
        for (int i = 0; i < LATENT; i++)
#pragma unroll
            for (int j = 0; j < HID; j++) h[j] = fmaf(z[i], W1r[i * HID + j], h[j]);
        float o = b2r;
#pragma unroll
        for (int j = 0; j < HID; j++) o = fmaf(tanh_fast(h[j]), W2r[j], o);
        float v = tanh_fast(o);
        dst[base + n] = v;             // default policy: keep in L2 for K3
        if (is_e) { ls += v; lq = fmaf(v, v, lq); }
        else      { lmin = fminf(lmin, v); lmax = fmaxf(lmax, v); }
    }

    __shared__ float redA[256];
    __shared__ float redB[256];
    if (is_e) {
        redA[tid] = ls; redB[tid] = lq; __syncthreads();
        for (int s = 128; s; s >>= 1) {
            if (tid < s) { redA[tid] += redA[tid + s]; redB[tid] += redB[tid + s]; }
            __syncthreads();
        }
        if (tid == 0) {
            int pid = blockIdx.y * gridDim.x + blockIdx.x;
            g_psum[pid] = redA[0];
            g_psumsq[pid] = redB[0];
        }
    } else {
        redA[tid] = lmin; redB[tid] = lmax; __syncthreads();
        for (int s = 128; s; s >>= 1) {
            if (tid < s) {
                redA[tid] = fminf(redA[tid], redA[tid + s]);
                redB[tid] = fmaxf(redB[tid], redB[tid + s]);
            }
            __syncthreads();
        }
        if (tid == 0) {
            atomicMin(&g_minbits[c], fenc(redA[0]));
            atomicMax(&g_maxbits[c], fenc(redB[0]));
        }
    }
}

// ---------------- K3: per-block stats finalize + transpose + PWL + noise ----------------
__global__ void __launch_bounds__(256) out_kernel(float* __restrict__ out) {
    __shared__ float sx[32][33];
    __shared__ float se[32][33];
    __shared__ float syp[32][21];
    __shared__ float smn[32];
    __shared__ float ssc[32];
    __shared__ double sds[256];
    __shared__ double sdq[256];
    __shared__ float sstats[2];  // mean, invstd

    const int tx = threadIdx.x, ty = threadIdx.y;
    const int tid = ty * 32 + tx;
    const int n0 = blockIdx.x * 32;
    const int c0 = blockIdx.y * 32;

    // --- stats prologue: deterministic fixed-order double reduce of 2048 partials (L2-resident) ---
    {
        double s = 0.0, q = 0.0;
#pragma unroll
        for (int i = 0; i < 8; i++) {
            int idx = tid + i * 256;
            s += (double)g_psum[idx];
            q += (double)g_psumsq[idx];
        }
        sds[tid] = s; sdq[tid] = q; __syncthreads();
        for (int k = 128; k; k >>= 1) {
            if (tid < k) { sds[tid] += sds[tid + k]; sdq[tid] += sdq[tid + k]; }
            __syncthreads();
        }
        if (tid == 0) {
            double CN = (double)C_CH * (double)N_PTS;
            double mean = sds[0] / CN;
            double var = (sdq[0] - sds[0] * sds[0] / CN) / (CN - 1.0);
            sstats[0] = (float)mean;
            sstats[1] = (float)(1.0 / sqrt(var));
        }
    }

    for (int idx = tid; idx < 32 * K_PWL; idx += 256) {
        int cl = idx / K_PWL, k = idx % K_PWL;
        syp[cl][k] = g_yp[(c0 + cl) * K_PWL + k];
    }
    if (tid < 32) {
        float mn = fdec(g_minbits[c0 + tid]);
        float mx = fdec(g_maxbits[c0 + tid]);
        smn[tid] = mn;
        ssc[tid] = 1.0f / (mx - mn);
    }
#pragma unroll
    for (int r = 0; r < 4; r++) {
        int cl = ty + r * 8;
        size_t off = (size_t)(c0 + cl) * N_PTS + n0 + tx;
        sx[cl][tx] = g_x[off];
        se[cl][tx] = g_e[off];
    }
    __syncthreads();

    const float mean = sstats[0], invstd = sstats[1];
    const float mn = smn[tx], sc = ssc[tx];
#pragma unroll
    for (int r = 0; r < 4; r++) {
        int nn = ty + r * 8;
        float xv = (sx[tx][nn] - mn) * sc;
        int cnt = 0;
#pragma unroll
        for (int k = 0; k < K_PWL; k++) cnt += (c_xp[k] < xv) ? 1 : 0;
        int j = min(max(cnt - 1, 0), K_PWL - 2);
        float x0 = c_xp[j], x1 = c_xp[j + 1];
        float y0 = syp[tx][j], y1 = syp[tx][j + 1];
        float y = y0 + (xv - x0) * (y1 - y0) / (x1 - x0 + 1e-7f);
        float ev = (se[tx][nn] - mean) * invstd;
        __stcs(&out[(size_t)(n0 + nn) * C_CH + c0 + tx], fmaf(0.1f, ev, y));
    }
}

// ---------------- launch ----------------
extern "C" void kernel_launch(void* const* d_in, const int* in_sizes, int n_in,
                              void* d_out, int out_size) {
    const float* zf  = (const float*)d_in[0];
    const float* zx  = (const float*)d_in[1];
    const float* ze  = (const float*)d_in[2];
    const float* Wx1 = (const float*)d_in[3];
    const float* bx1 = (const float*)d_in[4];
    const float* Wx2 = (const float*)d_in[5];
    const float* bx2 = (const float*)d_in[6];
    const float* We1 = (const float*)d_in[7];
    const float* be1 = (const float*)d_in[8];
    const float* We2 = (const float*)d_in[9];
    const float* be2 = (const float*)d_in[10];
    const float* Wf1 = (const float*)d_in[11];
    const float* bf1 = (const float*)d_in[12];
    const float* Wf2 = (const float*)d_in[13];
    const float* bf2 = (const float*)d_in[14];
    const void*  dirs = d_in[15];
    float* out = (float*)d_out;

    gen_pwl_kernel<<<1, 128>>>(zf, Wf1, bf1, Wf2, bf2, dirs);
    pass_xe_kernel<<<dim3(16, 128, 2), 256>>>(zx, Wx1, bx1, Wx2, bx2,
                                              ze, We1, be1, We2, be2);
    out_kernel<<<dim3(N_PTS / 32, C_CH / 32), dim3(32, 8)>>>(out);
}

// round 6
// speedup vs baseline: 1.0053x; 1.0053x over previous
#include <cuda_runtime.h>
#include <cuda_bf16.h>
#include <math.h>
#include <stdint.h>

#define C_CH   128
#define N_PTS  32768
#define K_PWL  20
#define LATENT 8
#define HID    8

// ---------------- scratch (static device memory; no allocations) ----------------
__device__ float g_x[(size_t)C_CH * N_PTS];     // raw x MLP outputs [C][N]
__device__ float g_e[(size_t)C_CH * N_PTS];     // raw e MLP outputs [C][N]
__device__ float g_yp[C_CH * K_PWL];            // per-channel sorted/flipped breakpoint ys
__device__ unsigned int g_minbits[C_CH];
__device__ unsigned int g_maxbits[C_CH];
__device__ float g_psum[2048];
__device__ float g_psumsq[2048];

// xp = linspace(0,1,20) in f32
#define XPV(k) ((float)((double)(k) / 19.0))
__constant__ float c_xp[K_PWL] = {
    XPV(0), XPV(1), XPV(2), XPV(3), XPV(4), XPV(5), XPV(6), XPV(7), XPV(8), XPV(9),
    XPV(10), XPV(11), XPV(12), XPV(13), XPV(14), XPV(15), XPV(16), XPV(17), XPV(18), XPV(19)
};

// ---------------- helpers ----------------
__device__ __forceinline__ unsigned int fenc(float f) {
    unsigned int u = __float_as_uint(f);
    return (u >> 31) ? ~u : (u | 0x80000000u);
}
__device__ __forceinline__ float fdec(unsigned int u) {
    return (u & 0x80000000u) ? __uint_as_float(u & 0x7FFFFFFFu) : __uint_as_float(~u);
}

// Fast, tight-absolute-error tanh: (e^{2x}-1)/(e^{2x}+1). abs err ~1e-7.
__device__ __forceinline__ float tanh_fast(float x) {
    x = fminf(fmaxf(x, -30.0f), 30.0f);
    float t = __expf(2.0f * x);
    return __fdividef(t - 1.0f, t + 1.0f);
}

// ---------------- K1: PWL generator (tiny) + min/max init ----------------
__global__ void gen_pwl_kernel(const float* __restrict__ zf,
                               const float* __restrict__ Wf1, const float* __restrict__ bf1,
                               const float* __restrict__ Wf2, const float* __restrict__ bf2,
                               const void* __restrict__ dirs_raw) {
    int c = threadIdx.x;  // 128 threads, one per channel
    __shared__ int mode;  // 0 = int32, 1 = uint8/bool, 2 = float32
    if (c == 0) {
        const unsigned char* b = (const unsigned char*)dirs_raw;
        bool off_zero = true, all01 = true;
        for (int i = 0; i < 128; i++) {
            unsigned char v = b[i];
            if ((i & 3) != 0 && v != 0) off_zero = false;
            if (v > 1) all01 = false;
        }
        mode = off_zero ? 0 : (all01 ? 1 : 2);
    }
    __syncthreads();

    float z[LATENT];
#pragma unroll
    for (int i = 0; i < LATENT; i++) z[i] = zf[c * LATENT + i];

    float h[HID];
#pragma unroll
    for (int j = 0; j < HID; j++) h[j] = bf1[j];
#pragma unroll
    for (int i = 0; i < LATENT; i++)
#pragma unroll
        for (int j = 0; j < HID; j++) h[j] = fmaf(z[i], Wf1[i * HID + j], h[j]);
#pragma unroll
    for (int j = 0; j < HID; j++) h[j] = tanhf(h[j]);

    float pts[K_PWL];
#pragma unroll
    for (int k = 0; k < K_PWL; k++) {
        float s = bf2[k];
#pragma unroll
        for (int j = 0; j < HID; j++) s = fmaf(h[j], Wf2[j * K_PWL + k], s);
        pts[k] = tanhf(s);
    }
    // insertion sort ascending
    for (int a = 1; a < K_PWL; a++) {
        float v = pts[a];
        int b = a - 1;
        while (b >= 0 && pts[b] > v) { pts[b + 1] = pts[b]; b--; }
        pts[b + 1] = v;
    }
    bool dir;
    if (mode == 0)      dir = ((const int*)dirs_raw)[c] != 0;
    else if (mode == 1) dir = ((const unsigned char*)dirs_raw)[c] != 0;
    else                dir = ((const float*)dirs_raw)[c] > 0.5f;

    for (int k = 0; k < K_PWL; k++)
        g_yp[c * K_PWL + k] = dir ? pts[k] : pts[K_PWL - 1 - k];

    g_minbits[c] = 0xFFFFFFFFu;
    g_maxbits[c] = 0u;
}

// ---------------- K2: fused x/e MLP pass (blockIdx.z selects) ----------------
// z==0: x MLP + per-channel min/max atomics
// z==1: e MLP + per-block sum/sumsq partials
__global__ void __launch_bounds__(256) pass_xe_kernel(
    const float* __restrict__ zx,
    const float* __restrict__ Wx1, const float* __restrict__ bx1,
    const float* __restrict__ Wx2, const float* __restrict__ bx2,
    const float* __restrict__ ze,
    const float* __restrict__ We1, const float* __restrict__ be1,
    const float* __restrict__ We2, const float* __restrict__ be2) {
    const bool is_e = (blockIdx.z != 0);
    const float* __restrict__ src = is_e ? ze : zx;
    const float* __restrict__ W1p = is_e ? We1 : Wx1;
    const float* __restrict__ b1p = is_e ? be1 : bx1;
    const float* __restrict__ W2p = is_e ? We2 : Wx2;
    const float* __restrict__ b2p = is_e ? be2 : bx2;
    float* __restrict__ dst = is_e ? g_e : g_x;

    float W1r[64];
#pragma unroll
    for (int i = 0; i < 64; i++) W1r[i] = __ldg(W1p + i);
    float b1r[HID], W2r[HID];
#pragma unroll
    for (int j = 0; j < HID; j++) { b1r[j] = __ldg(b1p + j); W2r[j] = __ldg(W2p + j); }
    float b2r = __ldg(b2p);

    const int c = blockIdx.y;
    const int tid = threadIdx.x;
    const size_t base = (size_t)c * N_PTS;
    const int n0 = blockIdx.x * 2048;

    float lmin = 1e30f, lmax = -1e30f;   // x stats
    float ls = 0.0f, lq = 0.0f;          // e stats
#pragma unroll
    for (int k = 0; k < 8; k++) {
        int n = n0 + k * 256 + tid;
        const float4* p = reinterpret_cast<const float4*>(src + (base + n) * LATENT);
        float4 a = __ldcs(p);          // streaming: don't pollute L2
        float4 bq = __ldcs(p + 1);
        float z[8] = {a.x, a.y, a.z, a.w, bq.x, bq.y, bq.z, bq.w};
        float h[HID];
#pragma unroll
        for (int j = 0; j < HID; j++) h[j] = b1r[j];
#pragma unroll
        for (int i = 0; i < LATENT; i++)
#pragma unroll
            for (int j = 0; j < HID; j++) h[j] = fmaf(z[i], W1r[i * HID + j], h[j]);
        float o = b2r;
#pragma unroll
        for (int j = 0; j < HID; j++) o = fmaf(tanh_fast(h[j]), W2r[j], o);
        float v = tanh_fast(o);
        dst[base + n] = v;             // default policy: keep in L2 for K3
        if (is_e) { ls += v; lq = fmaf(v, v, lq); }
        else      { lmin = fminf(lmin, v); lmax = fmaxf(lmax, v); }
    }

    __shared__ float redA[256];
    __shared__ float redB[256];
    if (is_e) {
        redA[tid] = ls; redB[tid] = lq; __syncthreads();
        for (int s = 128; s; s >>= 1) {
            if (tid < s) { redA[tid] += redA[tid + s]; redB[tid] += redB[tid + s]; }
            __syncthreads();
        }
        if (tid == 0) {
            int pid = blockIdx.y * gridDim.x + blockIdx.x;
            g_psum[pid] = redA[0];
            g_psumsq[pid] = redB[0];
        }
    } else {
        redA[tid] = lmin; redB[tid] = lmax; __syncthreads();
        for (int s = 128; s; s >>= 1) {
            if (tid < s) {
                redA[tid] = fminf(redA[tid], redA[tid + s]);
                redB[tid] = fmaxf(redB[tid], redB[tid + s]);
            }
            __syncthreads();
        }
        if (tid == 0) {
            atomicMin(&g_minbits[c], fenc(redA[0]));
            atomicMax(&g_maxbits[c], fenc(redB[0]));
        }
    }
}

// ---------------- K3: per-block stats finalize + transpose + PWL + noise ----------------
__global__ void __launch_bounds__(256) out_kernel(float* __restrict__ out) {
    __shared__ float sx[32][33];
    __shared__ float se[32][33];
    __shared__ float syp[32][21];
    __shared__ float smn[32];
    __shared__ float ssc[32];
    __shared__ double sds[256];
    __shared__ double sdq[256];
    __shared__ float sstats[2];  // mean, invstd

    const int tx = threadIdx.x, ty = threadIdx.y;
    const int tid = ty * 32 + tx;
    const int n0 = blockIdx.x * 32;
    const int c0 = blockIdx.y * 32;

    // --- stats prologue: deterministic fixed-order double reduce of 2048 partials (L2-resident) ---
    {
        double s = 0.0, q = 0.0;
#pragma unroll
        for (int i = 0; i < 8; i++) {
            int idx = tid + i * 256;
            s += (double)g_psum[idx];
            q += (double)g_psumsq[idx];
        }
        sds[tid] = s; sdq[tid] = q; __syncthreads();
        for (int k = 128; k; k >>= 1) {
            if (tid < k) { sds[tid] += sds[tid + k]; sdq[tid] += sdq[tid + k]; }
            __syncthreads();
        }
        if (tid == 0) {
            double CN = (double)C_CH * (double)N_PTS;
            double mean = sds[0] / CN;
            double var = (sdq[0] - sds[0] * sds[0] / CN) / (CN - 1.0);
            sstats[0] = (float)mean;
            sstats[1] = (float)(1.0 / sqrt(var));
        }
    }

    for (int idx = tid; idx < 32 * K_PWL; idx += 256) {
        int cl = idx / K_PWL, k = idx % K_PWL;
        syp[cl][k] = g_yp[(c0 + cl) * K_PWL + k];
    }
    if (tid < 32) {
        float mn = fdec(g_minbits[c0 + tid]);
        float mx = fdec(g_maxbits[c0 + tid]);
        smn[tid] = mn;
        ssc[tid] = 1.0f / (mx - mn);
    }
#pragma unroll
    for (int r = 0; r < 4; r++) {
        int cl = ty + r * 8;
        size_t off = (size_t)(c0 + cl) * N_PTS + n0 + tx;
        sx[cl][tx] = g_x[off];
        se[cl][tx] = g_e[off];
    }
    __syncthreads();

    const float mean = sstats[0], invstd = sstats[1];
    const float mn = smn[tx], sc = ssc[tx];
#pragma unroll
    for (int r = 0; r < 4; r++) {
        int nn = ty + r * 8;
        float xv = (sx[tx][nn] - mn) * sc;
        int cnt = 0;
#pragma unroll
        for (int k = 0; k < K_PWL; k++) cnt += (c_xp[k] < xv) ? 1 : 0;
        int j = min(max(cnt - 1, 0), K_PWL - 2);
        float x0 = c_xp[j], x1 = c_xp[j + 1];
        float y0 = syp[tx][j], y1 = syp[tx][j + 1];
        float y = y0 + (xv - x0) * (y1 - y0) / (x1 - x0 + 1e-7f);
        float ev = (se[tx][nn] - mean) * invstd;
        __stcs(&out[(size_t)(n0 + nn) * C_CH + c0 + tx], fmaf(0.1f, ev, y));
    }
}

// ---------------- launch ----------------
extern "C" void kernel_launch(void* const* d_in, const int* in_sizes, int n_in,
                              void* d_out, int out_size) {
    const float* zf  = (const float*)d_in[0];
    const float* zx  = (const float*)d_in[1];
    const float* ze  = (const float*)d_in[2];
    const float* Wx1 = (const float*)d_in[3];
    const float* bx1 = (const float*)d_in[4];
    const float* Wx2 = (const float*)d_in[5];
    const float* bx2 = (const float*)d_in[6];
    const float* We1 = (const float*)d_in[7];
    const float* be1 = (const float*)d_in[8];
    const float* We2 = (const float*)d_in[9];
    const float* be2 = (const float*)d_in[10];
    const float* Wf1 = (const float*)d_in[11];
    const float* bf1 = (const float*)d_in[12];
    const float* Wf2 = (const float*)d_in[13];
    const float* bf2 = (const float*)d_in[14];
    const void*  dirs = d_in[15];
    float* out = (float*)d_out;

    gen_pwl_kernel<<<1, 128>>>(zf, Wf1, bf1, Wf2, bf2, dirs);
    pass_xe_kernel<<<dim3(16, 128, 2), 256>>>(zx, Wx1, bx1, Wx2, bx2,
                                              ze, We1, be1, We2, be2);
    out_kernel<<<dim3(N_PTS / 32, C_CH / 32), dim3(32, 8)>>>(out);
}

// round 7
// speedup vs baseline: 1.4685x; 1.4607x over previous
#include <cuda_runtime.h>
#include <cuda_bf16.h>
#include <math.h>
#include <stdint.h>

#define C_CH   128
#define N_PTS  32768
#define K_PWL  20
#define LATENT 8
#define HID    8

// ---------------- scratch (static device memory; no allocations) ----------------
__device__ float g_x[(size_t)C_CH * N_PTS];     // raw x MLP outputs [C][N]
__device__ float g_e[(size_t)C_CH * N_PTS];     // raw e MLP outputs [C][N]
__device__ float g_yp[C_CH * K_PWL];            // per-channel sorted/flipped breakpoint ys
__device__ unsigned int g_minbits[C_CH];
__device__ unsigned int g_maxbits[C_CH];
__device__ float g_minv[C_CH];
__device__ float g_scale[C_CH];
__device__ float g_psum[2048];
__device__ float g_psumsq[2048];
__device__ float g_mean;
__device__ float g_invstd;
__device__ unsigned int g_done;

// xp = linspace(0,1,20) in f32
#define XPV(k) ((float)((double)(k) / 19.0))
__constant__ float c_xp[K_PWL] = {
    XPV(0), XPV(1), XPV(2), XPV(3), XPV(4), XPV(5), XPV(6), XPV(7), XPV(8), XPV(9),
    XPV(10), XPV(11), XPV(12), XPV(13), XPV(14), XPV(15), XPV(16), XPV(17), XPV(18), XPV(19)
};

// ---------------- helpers ----------------
__device__ __forceinline__ unsigned int fenc(float f) {
    unsigned int u = __float_as_uint(f);
    return (u >> 31) ? ~u : (u | 0x80000000u);
}
__device__ __forceinline__ float fdec(unsigned int u) {
    return (u & 0x80000000u) ? __uint_as_float(u & 0x7FFFFFFFu) : __uint_as_float(~u);
}

// Fast, tight-absolute-error tanh: (e^{2x}-1)/(e^{2x}+1). abs err ~1e-7.
__device__ __forceinline__ float tanh_fast(float x) {
    x = fminf(fmaxf(x, -30.0f), 30.0f);
    float t = __expf(2.0f * x);
    return __fdividef(t - 1.0f, t + 1.0f);
}

// ---------------- K1: PWL generator (tiny) + init ----------------
__global__ void gen_pwl_kernel(const float* __restrict__ zf,
                               const float* __restrict__ Wf1, const float* __restrict__ bf1,
                               const float* __restrict__ Wf2, const float* __restrict__ bf2,
                               const void* __restrict__ dirs_raw) {
    int c = threadIdx.x;  // 128 threads, one per channel
    // Parallel dtype detection for `directions`:
    //   bit0 set -> some byte at offset %4 != 0 is nonzero  (NOT int32 with 0/1 values)
    //   bit1 set -> some byte value > 1                     (NOT a 0/1 byte array)
    __shared__ unsigned int flags;
    if (c == 0) { flags = 0u; g_done = 0u; }
    __syncthreads();
    {
        unsigned char v = ((const unsigned char*)dirs_raw)[c];
        unsigned int f = 0u;
        if ((c & 3) != 0 && v != 0) f |= 1u;
        if (v > 1) f |= 2u;
        if (f) atomicOr(&flags, f);
    }
    __syncthreads();
    // mode: 0 = int32, 1 = uint8/bool, 2 = float32
    const int mode = (!(flags & 1u)) ? 0 : ((!(flags & 2u)) ? 1 : 2);

    float z[LATENT];
#pragma unroll
    for (int i = 0; i < LATENT; i++) z[i] = zf[c * LATENT + i];

    float h[HID];
#pragma unroll
    for (int j = 0; j < HID; j++) h[j] = bf1[j];
#pragma unroll
    for (int i = 0; i < LATENT; i++)
#pragma unroll
        for (int j = 0; j < HID; j++) h[j] = fmaf(z[i], Wf1[i * HID + j], h[j]);
#pragma unroll
    for (int j = 0; j < HID; j++) h[j] = tanh_fast(h[j]);

    float pts[K_PWL];
#pragma unroll
    for (int k = 0; k < K_PWL; k++) {
        float s = bf2[k];
#pragma unroll
        for (int j = 0; j < HID; j++) s = fmaf(h[j], Wf2[j * K_PWL + k], s);
        pts[k] = tanh_fast(s);
    }
    // insertion sort ascending
    for (int a = 1; a < K_PWL; a++) {
        float v = pts[a];
        int b = a - 1;
        while (b >= 0 && pts[b] > v) { pts[b + 1] = pts[b]; b--; }
        pts[b + 1] = v;
    }
    bool dir;
    if (mode == 0)      dir = ((const int*)dirs_raw)[c] != 0;
    else if (mode == 1) dir = ((const unsigned char*)dirs_raw)[c] != 0;
    else                dir = ((const float*)dirs_raw)[c] > 0.5f;

    for (int k = 0; k < K_PWL; k++)
        g_yp[c * K_PWL + k] = dir ? pts[k] : pts[K_PWL - 1 - k];

    g_minbits[c] = 0xFFFFFFFFu;
    g_maxbits[c] = 0u;
}

// ---------------- K2: x MLP + per-channel min/max ----------------
__global__ void __launch_bounds__(256) pass_x_kernel(
    const float* __restrict__ zx,
    const float* __restrict__ W1, const float* __restrict__ b1,
    const float* __restrict__ W2, const float* __restrict__ b2) {
    float W1r[64];
#pragma unroll
    for (int i = 0; i < 64; i++) W1r[i] = __ldg(W1 + i);
    float b1r[HID], W2r[HID];
#pragma unroll
    for (int j = 0; j < HID; j++) { b1r[j] = __ldg(b1 + j); W2r[j] = __ldg(W2 + j); }
    float b2r = __ldg(b2);

    const int c = blockIdx.y;
    const int tid = threadIdx.x;
    const size_t base = (size_t)c * N_PTS;
    const int n0 = blockIdx.x * 2048;

    float lmin = 1e30f, lmax = -1e30f;
#pragma unroll
    for (int k = 0; k < 8; k++) {
        int n = n0 + k * 256 + tid;
        const float4* p = reinterpret_cast<const float4*>(zx + (base + n) * LATENT);
        float4 a = p[0], bq = p[1];
        float z[8] = {a.x, a.y, a.z, a.w, bq.x, bq.y, bq.z, bq.w};
        float h[HID];
#pragma unroll
        for (int j = 0; j < HID; j++) h[j] = b1r[j];
#pragma unroll
        for (int i = 0; i < LATENT; i++)
#pragma unroll
            for (int j = 0; j < HID; j++) h[j] = fmaf(z[i], W1r[i * HID + j], h[j]);
        float o = b2r;
#pragma unroll
        for (int j = 0; j < HID; j++) o = fmaf(tanh_fast(h[j]), W2r[j], o);
        float xv = tanh_fast(o);
        g_x[base + n] = xv;
        lmin = fminf(lmin, xv);
        lmax = fmaxf(lmax, xv);
    }

    __shared__ float red[256];
    red[tid] = lmin; __syncthreads();
    for (int s = 128; s; s >>= 1) { if (tid < s) red[tid] = fminf(red[tid], red[tid + s]); __syncthreads(); }
    if (tid == 0) atomicMin(&g_minbits[c], fenc(red[0]));
    __syncthreads();
    red[tid] = lmax; __syncthreads();
    for (int s = 128; s; s >>= 1) { if (tid < s) red[tid] = fmaxf(red[tid], red[tid + s]); __syncthreads(); }
    if (tid == 0) atomicMax(&g_maxbits[c], fenc(red[0]));
}

// ---------------- K3: e MLP + global sum/sumsq partials + last-block finalize ----------------
__global__ void __launch_bounds__(256) pass_e_kernel(
    const float* __restrict__ ze,
    const float* __restrict__ W1, const float* __restrict__ b1,
    const float* __restrict__ W2, const float* __restrict__ b2) {
    float W1r[64];
#pragma unroll
    for (int i = 0; i < 64; i++) W1r[i] = __ldg(W1 + i);
    float b1r[HID], W2r[HID];
#pragma unroll
    for (int j = 0; j < HID; j++) { b1r[j] = __ldg(b1 + j); W2r[j] = __ldg(W2 + j); }
    float b2r = __ldg(b2);

    const int c = blockIdx.y;
    const int tid = threadIdx.x;
    const size_t base = (size_t)c * N_PTS;
    const int n0 = blockIdx.x * 2048;

    float ls = 0.0f, lq = 0.0f;
#pragma unroll
    for (int k = 0; k < 8; k++) {
        int n = n0 + k * 256 + tid;
        const float4* p = reinterpret_cast<const float4*>(ze + (base + n) * LATENT);
        float4 a = p[0], bq = p[1];
        float z[8] = {a.x, a.y, a.z, a.w, bq.x, bq.y, bq.z, bq.w};
        float h[HID];
#pragma unroll
        for (int j = 0; j < HID; j++) h[j] = b1r[j];
#pragma unroll
        for (int i = 0; i < LATENT; i++)
#pragma unroll
            for (int j = 0; j < HID; j++) h[j] = fmaf(z[i], W1r[i * HID + j], h[j]);
        float o = b2r;
#pragma unroll
        for (int j = 0; j < HID; j++) o = fmaf(tanh_fast(h[j]), W2r[j], o);
        float ev = tanh_fast(o);
        g_e[base + n] = ev;
        ls += ev;
        lq = fmaf(ev, ev, lq);
    }

    __shared__ float reds[256];
    __shared__ float redq[256];
    __shared__ bool amLast;
    reds[tid] = ls; redq[tid] = lq; __syncthreads();
    for (int s = 128; s; s >>= 1) {
        if (tid < s) { reds[tid] += reds[tid + s]; redq[tid] += redq[tid + s]; }
        __syncthreads();
    }
    if (tid == 0) {
        int pid = blockIdx.y * gridDim.x + blockIdx.x;
        g_psum[pid] = reds[0];
        g_psumsq[pid] = redq[0];
        __threadfence();                       // release partials
        unsigned int t = atomicAdd(&g_done, 1u);
        amLast = (t == 2048u - 1u);
    }
    __syncthreads();

    // Last block to finish performs the deterministic fixed-order fp64 reduce.
    if (amLast) {
        __threadfence();                       // acquire all partials
        __shared__ double sds[256];
        __shared__ double sdq[256];
        double s = 0.0, q = 0.0;
#pragma unroll
        for (int i = 0; i < 8; i++) {
            int idx = tid + i * 256;
            s += (double)g_psum[idx];
            q += (double)g_psumsq[idx];
        }
        sds[tid] = s; sdq[tid] = q; __syncthreads();
        for (int k = 128; k; k >>= 1) {
            if (tid < k) { sds[tid] += sds[tid + k]; sdq[tid] += sdq[tid + k]; }
            __syncthreads();
        }
        if (tid == 0) {
            double CN = (double)C_CH * (double)N_PTS;
            double mean = sds[0] / CN;
            double var = (sdq[0] - sds[0] * sds[0] / CN) / (CN - 1.0);
            g_mean = (float)mean;
            g_invstd = (float)(1.0 / sqrt(var));
            g_done = 0u;                       // reset for next graph replay
        }
        if (tid < C_CH) {
            float mn = fdec(g_minbits[tid]);   // pass_x completed before this kernel (stream order)
            float mx = fdec(g_maxbits[tid]);
            g_minv[tid] = mn;
            g_scale[tid] = 1.0f / (mx - mn);
        }
        __threadfence();                       // publish stats before kernel end (paranoia; launch boundary also fences)
    }
}

// ---------------- K4: transpose + PWL calibrate + noise ----------------
__global__ void __launch_bounds__(256) out_kernel(float* __restrict__ out) {
    __shared__ float sx[32][33];
    __shared__ float se[32][33];
    __shared__ float syp[32][21];
    __shared__ float smn[32];
    __shared__ float ssc[32];

    const int tx = threadIdx.x, ty = threadIdx.y;
    const int tid = ty * 32 + tx;
    const int n0 = blockIdx.x * 32;
    const int c0 = blockIdx.y * 32;

    for (int idx = tid; idx < 32 * K_PWL; idx += 256) {
        int cl = idx / K_PWL, k = idx % K_PWL;
        syp[cl][k] = g_yp[(c0 + cl) * K_PWL + k];
    }
    if (tid < 32) {
        smn[tid] = g_minv[c0 + tid];
        ssc[tid] = g_scale[c0 + tid];
    }
#pragma unroll
    for (int r = 0; r < 4; r++) {
        int cl = ty + r * 8;
        size_t off = (size_t)(c0 + cl) * N_PTS + n0 + tx;
        sx[cl][tx] = g_x[off];
        se[cl][tx] = g_e[off];
    }
    __syncthreads();

    const float mean = g_mean, invstd = g_invstd;
    const float mn = smn[tx], sc = ssc[tx];
#pragma unroll
    for (int r = 0; r < 4; r++) {
        int nn = ty + r * 8;
        float xv = (sx[tx][nn] - mn) * sc;
        int cnt = 0;
#pragma unroll
        for (int k = 0; k < K_PWL; k++) cnt += (c_xp[k] < xv) ? 1 : 0;
        int j = min(max(cnt - 1, 0), K_PWL - 2);
        float x0 = c_xp[j], x1 = c_xp[j + 1];
        float y0 = syp[tx][j], y1 = syp[tx][j + 1];
        float y = y0 + (xv - x0) * (y1 - y0) / (x1 - x0 + 1e-7f);
        float ev = (se[tx][nn] - mean) * invstd;
        out[(size_t)(n0 + nn) * C_CH + c0 + tx] = fmaf(0.1f, ev, y);
    }
}

// ---------------- launch ----------------
extern "C" void kernel_launch(void* const* d_in, const int* in_sizes, int n_in,
                              void* d_out, int out_size) {
    const float* zf  = (const float*)d_in[0];
    const float* zx  = (const float*)d_in[1];
    const float* ze  = (const float*)d_in[2];
    const float* Wx1 = (const float*)d_in[3];
    const float* bx1 = (const float*)d_in[4];
    const float* Wx2 = (const float*)d_in[5];
    const float* bx2 = (const float*)d_in[6];
    const float* We1 = (const float*)d_in[7];
    const float* be1 = (const float*)d_in[8];
    const float* We2 = (const float*)d_in[9];
    const float* be2 = (const float*)d_in[10];
    const float* Wf1 = (const float*)d_in[11];
    const float* bf1 = (const float*)d_in[12];
    const float* Wf2 = (const float*)d_in[13];
    const float* bf2 = (const float*)d_in[14];
    const void*  dirs = d_in[15];
    float* out = (float*)d_out;

    gen_pwl_kernel<<<1, 128>>>(zf, Wf1, bf1, Wf2, bf2, dirs);
    pass_x_kernel<<<dim3(16, 128), 256>>>(zx, Wx1, bx1, Wx2, bx2);
    pass_e_kernel<<<dim3(16, 128), 256>>>(ze, We1, be1, We2, be2);
    out_kernel<<<dim3(N_PTS / 32, C_CH / 32), dim3(32, 8)>>>(out);
}

// round 8
// speedup vs baseline: 1.6897x; 1.1507x over previous
#include <cuda_runtime.h>
#include <cuda_bf16.h>
#include <math.h>
#include <stdint.h>

#define C_CH   128
#define N_PTS  32768
#define K_PWL  20
#define LATENT 8
#define HID    8
#define NSEG   (K_PWL - 1)

// ---------------- scratch (static device memory; no allocations) ----------------
__device__ float g_x[(size_t)C_CH * N_PTS];     // raw x MLP outputs [C][N]
__device__ float g_e[(size_t)C_CH * N_PTS];     // raw e MLP outputs [C][N]
__device__ float g_slope[C_CH * NSEG];          // per-channel PWL segment slopes
__device__ float g_icept[C_CH * NSEG];          // per-channel PWL segment intercepts
__device__ unsigned int g_minbits[C_CH];
__device__ unsigned int g_maxbits[C_CH];
__device__ float g_minv[C_CH];
__device__ float g_scale[C_CH];
__device__ float g_psum[2048];
__device__ float g_psumsq[2048];
__device__ float g_eA;   // 0.1 * invstd
__device__ float g_eB;   // -0.1 * mean * invstd
__device__ unsigned int g_done;

// xp = linspace(0,1,20) in f32
#define XPV(k) ((float)((double)(k) / 19.0))
__constant__ float c_xp[K_PWL] = {
    XPV(0), XPV(1), XPV(2), XPV(3), XPV(4), XPV(5), XPV(6), XPV(7), XPV(8), XPV(9),
    XPV(10), XPV(11), XPV(12), XPV(13), XPV(14), XPV(15), XPV(16), XPV(17), XPV(18), XPV(19)
};

// ---------------- helpers ----------------
__device__ __forceinline__ unsigned int fenc(float f) {
    unsigned int u = __float_as_uint(f);
    return (u >> 31) ? ~u : (u | 0x80000000u);
}
__device__ __forceinline__ float fdec(unsigned int u) {
    return (u & 0x80000000u) ? __uint_as_float(u & 0x7FFFFFFFu) : __uint_as_float(~u);
}

// Fast, tight-absolute-error tanh: (e^{2x}-1)/(e^{2x}+1). abs err ~1e-7.
__device__ __forceinline__ float tanh_fast(float x) {
    x = fminf(fmaxf(x, -30.0f), 30.0f);
    float t = __expf(2.0f * x);
    return __fdividef(t - 1.0f, t + 1.0f);
}

// ---------------- K1: PWL generator (tiny) + slope/intercept tables + init ----------------
__global__ void gen_pwl_kernel(const float* __restrict__ zf,
                               const float* __restrict__ Wf1, const float* __restrict__ bf1,
                               const float* __restrict__ Wf2, const float* __restrict__ bf2,
                               const void* __restrict__ dirs_raw) {
    int c = threadIdx.x;  // 128 threads, one per channel
    // Parallel dtype detection for `directions`:
    //   bit0 -> some byte at offset %4 != 0 is nonzero  (NOT int32 0/1)
    //   bit1 -> some byte value > 1                     (NOT a 0/1 byte array)
    __shared__ unsigned int flags;
    if (c == 0) { flags = 0u; g_done = 0u; }
    __syncthreads();
    {
        unsigned char v = ((const unsigned char*)dirs_raw)[c];
        unsigned int f = 0u;
        if ((c & 3) != 0 && v != 0) f |= 1u;
        if (v > 1) f |= 2u;
        if (f) atomicOr(&flags, f);
    }
    __syncthreads();
    // mode: 0 = int32, 1 = uint8/bool, 2 = float32
    const int mode = (!(flags & 1u)) ? 0 : ((!(flags & 2u)) ? 1 : 2);

    float z[LATENT];
#pragma unroll
    for (int i = 0; i < LATENT; i++) z[i] = zf[c * LATENT + i];

    float h[HID];
#pragma unroll
    for (int j = 0; j < HID; j++) h[j] = bf1[j];
#pragma unroll
    for (int i = 0; i < LATENT; i++)
#pragma unroll
        for (int j = 0; j < HID; j++) h[j] = fmaf(z[i], Wf1[i * HID + j], h[j]);
#pragma unroll
    for (int j = 0; j < HID; j++) h[j] = tanh_fast(h[j]);

    float pts[K_PWL];
#pragma unroll
    for (int k = 0; k < K_PWL; k++) {
        float s = bf2[k];
#pragma unroll
        for (int j = 0; j < HID; j++) s = fmaf(h[j], Wf2[j * K_PWL + k], s);
        pts[k] = tanh_fast(s);
    }
    // insertion sort ascending
    for (int a = 1; a < K_PWL; a++) {
        float v = pts[a];
        int b = a - 1;
        while (b >= 0 && pts[b] > v) { pts[b + 1] = pts[b]; b--; }
        pts[b + 1] = v;
    }
    bool dir;
    if (mode == 0)      dir = ((const int*)dirs_raw)[c] != 0;
    else if (mode == 1) dir = ((const unsigned char*)dirs_raw)[c] != 0;
    else                dir = ((const float*)dirs_raw)[c] > 0.5f;

    // Per-segment slope/intercept: y(xv) = sl*xv + ic on [xp[k], xp[k+1]]
    for (int k = 0; k < NSEG; k++) {
        float y0 = dir ? pts[k]     : pts[K_PWL - 1 - k];
        float y1 = dir ? pts[k + 1] : pts[K_PWL - 2 - k];
        float sl = (y1 - y0) / (c_xp[k + 1] - c_xp[k] + 1e-7f);
        g_slope[c * NSEG + k] = sl;
        g_icept[c * NSEG + k] = fmaf(-c_xp[k], sl, y0);
    }

    g_minbits[c] = 0xFFFFFFFFu;
    g_maxbits[c] = 0u;
}

// ---------------- K2: x MLP + per-channel min/max ----------------
__global__ void __launch_bounds__(256) pass_x_kernel(
    const float* __restrict__ zx,
    const float* __restrict__ W1, const float* __restrict__ b1,
    const float* __restrict__ W2, const float* __restrict__ b2) {
    float W1r[64];
#pragma unroll
    for (int i = 0; i < 64; i++) W1r[i] = __ldg(W1 + i);
    float b1r[HID], W2r[HID];
#pragma unroll
    for (int j = 0; j < HID; j++) { b1r[j] = __ldg(b1 + j); W2r[j] = __ldg(W2 + j); }
    float b2r = __ldg(b2);

    const int c = blockIdx.y;
    const int tid = threadIdx.x;
    const size_t base = (size_t)c * N_PTS;
    const int n0 = blockIdx.x * 2048;

    float lmin = 1e30f, lmax = -1e30f;
#pragma unroll
    for (int k = 0; k < 8; k++) {
        int n = n0 + k * 256 + tid;
        const float4* p = reinterpret_cast<const float4*>(zx + (base + n) * LATENT);
        float4 a = p[0], bq = p[1];
        float z[8] = {a.x, a.y, a.z, a.w, bq.x, bq.y, bq.z, bq.w};
        float h[HID];
#pragma unroll
        for (int j = 0; j < HID; j++) h[j] = b1r[j];
#pragma unroll
        for (int i = 0; i < LATENT; i++)
#pragma unroll
            for (int j = 0; j < HID; j++) h[j] = fmaf(z[i], W1r[i * HID + j], h[j]);
        float o = b2r;
#pragma unroll
        for (int j = 0; j < HID; j++) o = fmaf(tanh_fast(h[j]), W2r[j], o);
        float xv = tanh_fast(o);
        g_x[base + n] = xv;
        lmin = fminf(lmin, xv);
        lmax = fmaxf(lmax, xv);
    }

    __shared__ float red[256];
    red[tid] = lmin; __syncthreads();
    for (int s = 128; s; s >>= 1) { if (tid < s) red[tid] = fminf(red[tid], red[tid + s]); __syncthreads(); }
    if (tid == 0) atomicMin(&g_minbits[c], fenc(red[0]));
    __syncthreads();
    red[tid] = lmax; __syncthreads();
    for (int s = 128; s; s >>= 1) { if (tid < s) red[tid] = fmaxf(red[tid], red[tid + s]); __syncthreads(); }
    if (tid == 0) atomicMax(&g_maxbits[c], fenc(red[0]));
}

// ---------------- K3: e MLP + global sum/sumsq partials + last-block finalize ----------------
__global__ void __launch_bounds__(256) pass_e_kernel(
    const float* __restrict__ ze,
    const float* __restrict__ W1, const float* __restrict__ b1,
    const float* __restrict__ W2, const float* __restrict__ b2) {
    float W1r[64];
#pragma unroll
    for (int i = 0; i < 64; i++) W1r[i] = __ldg(W1 + i);
    float b1r[HID], W2r[HID];
#pragma unroll
    for (int j = 0; j < HID; j++) { b1r[j] = __ldg(b1 + j); W2r[j] = __ldg(W2 + j); }
    float b2r = __ldg(b2);

    const int c = blockIdx.y;
    const int tid = threadIdx.x;
    const size_t base = (size_t)c * N_PTS;
    const int n0 = blockIdx.x * 2048;

    float ls = 0.0f, lq = 0.0f;
#pragma unroll
    for (int k = 0; k < 8; k++) {
        int n = n0 + k * 256 + tid;
        const float4* p = reinterpret_cast<const float4*>(ze + (base + n) * LATENT);
        float4 a = p[0], bq = p[1];
        float z[8] = {a.x, a.y, a.z, a.w, bq.x, bq.y, bq.z, bq.w};
        float h[HID];
#pragma unroll
        for (int j = 0; j < HID; j++) h[j] = b1r[j];
#pragma unroll
        for (int i = 0; i < LATENT; i++)
#pragma unroll
            for (int j = 0; j < HID; j++) h[j] = fmaf(z[i], W1r[i * HID + j], h[j]);
        float o = b2r;
#pragma unroll
        for (int j = 0; j < HID; j++) o = fmaf(tanh_fast(h[j]), W2r[j], o);
        float ev = tanh_fast(o);
        g_e[base + n] = ev;
        ls += ev;
        lq = fmaf(ev, ev, lq);
    }

    __shared__ float reds[256];
    __shared__ float redq[256];
    __shared__ bool amLast;
    reds[tid] = ls; redq[tid] = lq; __syncthreads();
    for (int s = 128; s; s >>= 1) {
        if (tid < s) { reds[tid] += reds[tid + s]; redq[tid] += redq[tid + s]; }
        __syncthreads();
    }
    if (tid == 0) {
        int pid = blockIdx.y * gridDim.x + blockIdx.x;
        g_psum[pid] = reds[0];
        g_psumsq[pid] = redq[0];
        __threadfence();                       // release partials
        unsigned int t = atomicAdd(&g_done, 1u);
        amLast = (t == 2048u - 1u);
    }
    __syncthreads();

    // Last block performs the deterministic fixed-order fp64 reduce.
    if (amLast) {
        __threadfence();                       // acquire all partials
        __shared__ double sds[256];
        __shared__ double sdq[256];
        double s = 0.0, q = 0.0;
#pragma unroll
        for (int i = 0; i < 8; i++) {
            int idx = tid + i * 256;
            s += (double)g_psum[idx];
            q += (double)g_psumsq[idx];
        }
        sds[tid] = s; sdq[tid] = q; __syncthreads();
        for (int k = 128; k; k >>= 1) {
            if (tid < k) { sds[tid] += sds[tid + k]; sdq[tid] += sdq[tid + k]; }
            __syncthreads();
        }
        if (tid == 0) {
            double CN = (double)C_CH * (double)N_PTS;
            double mean = sds[0] / CN;
            double var = (sdq[0] - sds[0] * sds[0] / CN) / (CN - 1.0);
            double invstd = 1.0 / sqrt(var);
            g_eA = (float)(0.1 * invstd);
            g_eB = (float)(-0.1 * mean * invstd);
            g_done = 0u;                       // reset for next graph replay
        }
        if (tid < C_CH) {
            float mn = fdec(g_minbits[tid]);   // pass_x completed before this kernel (stream order)
            float mx = fdec(g_maxbits[tid]);
            g_minv[tid] = mn;
            g_scale[tid] = 1.0f / (mx - mn);
        }
        __threadfence();
    }
}

// ---------------- K4: transpose + direct-index PWL + noise ----------------
// Block covers 32 channels x 128 n (4 sub-tiles of 32x32).
__global__ void __launch_bounds__(256) out_kernel(float* __restrict__ out) {
    __shared__ float sx[32][33];
    __shared__ float se[32][33];
    __shared__ float ssl[32][NSEG + 1];
    __shared__ float ssb[32][NSEG + 1];
    __shared__ float smn[32];
    __shared__ float ssc[32];

    const int tx = threadIdx.x, ty = threadIdx.y;
    const int tid = ty * 32 + tx;
    const int nb = blockIdx.x * 128;
    const int c0 = blockIdx.y * 32;

    for (int idx = tid; idx < 32 * NSEG; idx += 256) {
        int cl = idx / NSEG, k = idx % NSEG;
        ssl[cl][k] = g_slope[(c0 + cl) * NSEG + k];
        ssb[cl][k] = g_icept[(c0 + cl) * NSEG + k];
    }
    if (tid < 32) {
        smn[tid] = g_minv[c0 + tid];
        ssc[tid] = g_scale[c0 + tid];
    }
    const float eA = g_eA, eB = g_eB;
    __syncthreads();

    const float mn = smn[tx], sc = ssc[tx];

#pragma unroll
    for (int t = 0; t < 4; t++) {
        const int n0 = nb + t * 32;
#pragma unroll
        for (int r = 0; r < 4; r++) {
            int cl = ty + r * 8;
            size_t off = (size_t)(c0 + cl) * N_PTS + n0 + tx;
            sx[cl][tx] = g_x[off];
            se[cl][tx] = g_e[off];
        }
        __syncthreads();
#pragma unroll
        for (int r = 0; r < 4; r++) {
            int nn = ty + r * 8;
            float xv = (sx[tx][nn] - mn) * sc;
            int j = min(max(__float2int_rd(xv * 19.0f), 0), NSEG - 1);
            float y = fmaf(xv, ssl[tx][j], ssb[tx][j]);
            out[(size_t)(n0 + nn) * C_CH + c0 + tx] = fmaf(se[tx][nn], eA, y + eB);
        }
        __syncthreads();
    }
}

// ---------------- launch ----------------
extern "C" void kernel_launch(void* const* d_in, const int* in_sizes, int n_in,
                              void* d_out, int out_size) {
    const float* zf  = (const float*)d_in[0];
    const float* zx  = (const float*)d_in[1];
    const float* ze  = (const float*)d_in[2];
    const float* Wx1 = (const float*)d_in[3];
    const float* bx1 = (const float*)d_in[4];
    const float* Wx2 = (const float*)d_in[5];
    const float* bx2 = (const float*)d_in[6];
    const float* We1 = (const float*)d_in[7];
    const float* be1 = (const float*)d_in[8];
    const float* We2 = (const float*)d_in[9];
    const float* be2 = (const float*)d_in[10];
    const float* Wf1 = (const float*)d_in[11];
    const float* bf1 = (const float*)d_in[12];
    const float* Wf2 = (const float*)d_in[13];
    const float* bf2 = (const float*)d_in[14];
    const void*  dirs = d_in[15];
    float* out = (float*)d_out;

    gen_pwl_kernel<<<1, 128>>>(zf, Wf1, bf1, Wf2, bf2, dirs);
    pass_x_kernel<<<dim3(16, 128), 256>>>(zx, Wx1, bx1, Wx2, bx2);
    pass_e_kernel<<<dim3(16, 128), 256>>>(ze, We1, be1, We2, be2);
    out_kernel<<<dim3(N_PTS / 128, C_CH / 32), dim3(32, 8)>>>(out);
}